// round 7
// baseline (speedup 1.0000x reference)
#include <cuda_runtime.h>
#include <cuda_bf16.h>

// Problem constants (match reference_code)
#define N_L   90
#define N_B   20
#define N_MU  46
#define N_LF  51
#define N_OUTK (N_LF - N_MU + 1)          // 6
#define NBINS (N_L * N_B * N_MU)          // 82800
#define N_LB  (N_L * N_B)                 // 1800
#define NOUT  (N_LB * N_OUTK)             // 10800

#define MN0  (-90.0f)
#define MN1  (-12.0f)
#define MN2  (7.0f)

#define THREADS        256
#define PER_THREAD     8
#define PART_PER_BLOCK (THREADS * PER_THREAD)   // 2048

// Zero-initialized at module load; re-zeroed by conv_zero_kernel (each (l,b)
// thread zeroes the 46-entry slice it just consumed), so every call /
// graph replay starts from a zeroed histogram. Deterministic.
static __device__ float g_hist[NBINS];

__device__ __forceinline__ int bin_of(float x, float y, float z,
                                      float idx0, float idx1, float idx2) {
    int i0 = __float2int_rn((x - MN0) * idx0);
    int i1 = __float2int_rn((y - MN1) * idx1);
    int i2 = __float2int_rn((z - MN2) * idx2);
    bool ok = (unsigned)i0 < (unsigned)N_L &&
              (unsigned)i1 < (unsigned)N_B &&
              (unsigned)i2 < (unsigned)N_MU;
    return ok ? (i0 * (N_B * N_MU) + i1 * N_MU + i2) : -1;
}

__device__ __forceinline__ void red_add(int b, float m) {
    if (b >= 0) {
        // No-return global reduction (REDG), not ATOMG.
        asm volatile("red.global.add.f32 [%0], %1;"
                     :: "l"(&g_hist[b]), "f"(m) : "memory");
    }
}

// Block owns 2048 contiguous particles. Coords AND masses staged through smem
// with fully-coalesced float4 loads; compute phase is LDS -> 8 bin computes ->
// 8 back-to-back REDs (no LDG in the dependency chain).
__global__ void __launch_bounds__(THREADS)
hist_kernel(const float* __restrict__ lbm,
            const float* __restrict__ mass,
            int n) {
    __shared__ float sc[PART_PER_BLOCK * 3];   // 24 KB coords
    __shared__ float sm[PART_PER_BLOCK];       //  8 KB masses

    const float dx0 = (90.0f - (-90.0f)) / (float)(N_L - 1);
    const float dx1 = (12.0f - (-12.0f)) / (float)(N_B - 1);
    const float dx2 = (16.0f - 7.0f) / (float)(N_MU - 1);
    const float idx0 = 1.0f / dx0;
    const float idx1 = 1.0f / dx1;
    const float idx2 = 1.0f / dx2;

    const int t   = threadIdx.x;
    const int bs  = blockIdx.x * PART_PER_BLOCK;        // block start particle
    const int cnt = min(PART_PER_BLOCK, n - bs);

    if (cnt == PART_PER_BLOCK) {
        const float4* c4 = (const float4*)(lbm + (size_t)bs * 3);
        float4* s4 = (float4*)sc;
#pragma unroll
        for (int i = 0; i < 6; i++) s4[t + THREADS * i] = c4[t + THREADS * i];
        const float4* m4 = (const float4*)(mass + bs);
        float4* sm4 = (float4*)sm;
        sm4[t + THREADS * 0] = m4[t + THREADS * 0];
        sm4[t + THREADS * 1] = m4[t + THREADS * 1];
    } else {
        for (int i = t; i < cnt * 3; i += THREADS) sc[i] = lbm[(size_t)bs * 3 + i];
        for (int i = t; i < cnt;     i += THREADS) sm[i] = mass[bs + i];
    }
    __syncthreads();

    if (cnt == PART_PER_BLOCK) {
        int   b[PER_THREAD];
        float m[PER_THREAD];
#pragma unroll
        for (int j = 0; j < PER_THREAD; j++) {
            int p = t + THREADS * j;                    // bank-conflict-free (stride 3)
            float x = sc[3 * p + 0];
            float y = sc[3 * p + 1];
            float z = sc[3 * p + 2];
            b[j] = bin_of(x, y, z, idx0, idx1, idx2);
            m[j] = sm[p];
        }
        // Uninterrupted RED burst.
#pragma unroll
        for (int j = 0; j < PER_THREAD; j++) red_add(b[j], m[j]);
    } else {
#pragma unroll
        for (int j = 0; j < PER_THREAD; j++) {
            int p = t + THREADS * j;
            if (p < cnt) {
                int bb = bin_of(sc[3 * p + 0], sc[3 * p + 1], sc[3 * p + 2],
                                idx0, idx1, idx2);
                red_add(bb, sm[p]);
            }
        }
    }
}

// One thread per (l,b) pair: reads its 46-entry hist slice, emits the 6
// convolution outputs, then zeroes the slice for the next call/replay.
__global__ void conv_zero_kernel(const float* __restrict__ lf,
                                 float* __restrict__ out) {
    __shared__ float s_lf[N_LF];
    int t = threadIdx.x;
    if (t < N_LF) s_lf[t] = lf[t];
    __syncthreads();

    int lb = blockIdx.x * blockDim.x + t;
    if (lb >= N_LB) return;

    float* h = &g_hist[lb * N_MU];
    float acc[N_OUTK];
#pragma unroll
    for (int k = 0; k < N_OUTK; k++) acc[k] = 0.0f;
#pragma unroll
    for (int i = 0; i < N_MU; i++) {
        float hv = h[i];
#pragma unroll
        for (int k = 0; k < N_OUTK; k++) {
            acc[k] = fmaf(hv, s_lf[k + (N_MU - 1) - i], acc[k]);
        }
    }
#pragma unroll
    for (int k = 0; k < N_OUTK; k++) out[lb * N_OUTK + k] = acc[k];
    // Zero the slice this thread owns (next replay starts clean).
#pragma unroll
    for (int i = 0; i < N_MU; i++) h[i] = 0.0f;
}

extern "C" void kernel_launch(void* const* d_in, const int* in_sizes, int n_in,
                              void* d_out, int out_size) {
    const float* lbm  = (const float*)d_in[0];   // [N,3] float32
    const float* mass = (const float*)d_in[1];   // [N]   float32
    const float* lf   = (const float*)d_in[2];   // [51]  float32
    float* out = (float*)d_out;                  // [90,20,6] float32

    int n = in_sizes[1];
    int grid = (n + PART_PER_BLOCK - 1) / PART_PER_BLOCK;
    if (grid < 1) grid = 1;

    hist_kernel<<<grid, THREADS>>>(lbm, mass, n);

    conv_zero_kernel<<<(N_LB + 255) / 256, 256>>>(lf, out);
}

// round 8
// speedup vs baseline: 1.0611x; 1.0611x over previous
#include <cuda_runtime.h>
#include <cuda_bf16.h>

// Problem constants (match reference_code)
#define N_L   90
#define N_B   20
#define N_MU  46
#define N_LF  51
#define N_OUTK (N_LF - N_MU + 1)          // 6
#define NBINS (N_L * N_B * N_MU)          // 82800
#define N_LB  (N_L * N_B)                 // 1800
#define NOUT  (N_LB * N_OUTK)             // 10800

#define MN0  (-90.0f)
#define MN1  (-12.0f)
#define MN2  (7.0f)

#define THREADS        256
#define PER_THREAD     8
#define PART_PER_BLOCK (THREADS * PER_THREAD)   // 2048

// conv_zero epilogue shape
#define LB_PER_BLOCK   32                        // 32*46 = 1472 bins/block
#define CONV_THREADS   (LB_PER_BLOCK * N_OUTK)   // 192 active conv threads

// Zero-initialized at module load; re-zeroed by conv_zero_kernel (each block
// zeroes exactly the bin slices it alone consumed), so every call / graph
// replay starts from a zeroed histogram. Deterministic.
static __device__ float g_hist[NBINS];

__device__ __forceinline__ int bin_of(float x, float y, float z,
                                      float idx0, float idx1, float idx2) {
    int i0 = __float2int_rn((x - MN0) * idx0);
    int i1 = __float2int_rn((y - MN1) * idx1);
    int i2 = __float2int_rn((z - MN2) * idx2);
    bool ok = (unsigned)i0 < (unsigned)N_L &&
              (unsigned)i1 < (unsigned)N_B &&
              (unsigned)i2 < (unsigned)N_MU;
    return ok ? (i0 * (N_B * N_MU) + i1 * N_MU + i2) : -1;
}

__device__ __forceinline__ void red_add(int b, float m) {
    if (b >= 0) {
        // No-return global reduction (REDG), not ATOMG.
        asm volatile("red.global.add.f32 [%0], %1;"
                     :: "l"(&g_hist[b]), "f"(m) : "memory");
    }
}

// Block owns 2048 contiguous particles. Coords AND masses staged through smem
// with fully-coalesced float4 loads; compute phase is LDS -> 8 bin computes ->
// 8 back-to-back REDs (no LDG in the dependency chain). (Measured ~134us.)
__global__ void __launch_bounds__(THREADS)
hist_kernel(const float* __restrict__ lbm,
            const float* __restrict__ mass,
            int n) {
    __shared__ float sc[PART_PER_BLOCK * 3];   // 24 KB coords
    __shared__ float sm[PART_PER_BLOCK];       //  8 KB masses

    const float dx0 = (90.0f - (-90.0f)) / (float)(N_L - 1);
    const float dx1 = (12.0f - (-12.0f)) / (float)(N_B - 1);
    const float dx2 = (16.0f - 7.0f) / (float)(N_MU - 1);
    const float idx0 = 1.0f / dx0;
    const float idx1 = 1.0f / dx1;
    const float idx2 = 1.0f / dx2;

    const int t   = threadIdx.x;
    const int bs  = blockIdx.x * PART_PER_BLOCK;        // block start particle
    const int cnt = min(PART_PER_BLOCK, n - bs);

    if (cnt == PART_PER_BLOCK) {
        const float4* c4 = (const float4*)(lbm + (size_t)bs * 3);
        float4* s4 = (float4*)sc;
#pragma unroll
        for (int i = 0; i < 6; i++) s4[t + THREADS * i] = c4[t + THREADS * i];
        const float4* m4 = (const float4*)(mass + bs);
        float4* sm4 = (float4*)sm;
        sm4[t + THREADS * 0] = m4[t + THREADS * 0];
        sm4[t + THREADS * 1] = m4[t + THREADS * 1];
    } else {
        for (int i = t; i < cnt * 3; i += THREADS) sc[i] = lbm[(size_t)bs * 3 + i];
        for (int i = t; i < cnt;     i += THREADS) sm[i] = mass[bs + i];
    }
    __syncthreads();

    if (cnt == PART_PER_BLOCK) {
        int   b[PER_THREAD];
        float m[PER_THREAD];
#pragma unroll
        for (int j = 0; j < PER_THREAD; j++) {
            int p = t + THREADS * j;                    // bank-conflict-free (stride 3)
            float x = sc[3 * p + 0];
            float y = sc[3 * p + 1];
            float z = sc[3 * p + 2];
            b[j] = bin_of(x, y, z, idx0, idx1, idx2);
            m[j] = sm[p];
        }
        // Uninterrupted RED burst.
#pragma unroll
        for (int j = 0; j < PER_THREAD; j++) red_add(b[j], m[j]);
    } else {
#pragma unroll
        for (int j = 0; j < PER_THREAD; j++) {
            int p = t + THREADS * j;
            if (p < cnt) {
                int bb = bin_of(sc[3 * p + 0], sc[3 * p + 1], sc[3 * p + 2],
                                idx0, idx1, idx2);
                red_add(bb, sm[p]);
            }
        }
    }
}

// Each block owns LB_PER_BLOCK=32 (l,b) pairs: threads 0..191 compute one
// (lb,k) output each; then the WHOLE block zeroes its own 1472-bin slice
// with coalesced float4 stores. No cross-block hazards: a block only zeroes
// slices it alone read.
__global__ void __launch_bounds__(THREADS)
conv_zero_kernel(const float* __restrict__ lf, float* __restrict__ out) {
    __shared__ float s_lf[N_LF];
    int t = threadIdx.x;
    if (t < N_LF) s_lf[t] = lf[t];
    __syncthreads();

    const int lb0 = blockIdx.x * LB_PER_BLOCK;

    if (t < CONV_THREADS) {
        int lb = lb0 + t / N_OUTK;
        if (lb < N_LB) {
            int k = t % N_OUTK;
            const float* h = &g_hist[lb * N_MU];
            float s = 0.0f;
#pragma unroll
            for (int i = 0; i < N_MU; i++) {
                s = fmaf(h[i], s_lf[k + (N_MU - 1) - i], s);
            }
            out[lb * N_OUTK + k] = s;
        }
    }
    __syncthreads();

    // Zero this block's slice: bins [lb0*46, (lb0+32)*46) = 1472 floats = 368 float4.
    {
        int base_f = lb0 * N_MU;                         // multiple of 1472 -> 16B aligned
        int nf = min(LB_PER_BLOCK * N_MU, NBINS - base_f);
        float4* z4 = (float4*)&g_hist[base_f];
        int n4 = nf / 4;                                 // N_MU*LB_PER_BLOCK % 4 == 0
        for (int i = t; i < n4; i += THREADS) {
            z4[i] = make_float4(0.f, 0.f, 0.f, 0.f);
        }
    }
}

extern "C" void kernel_launch(void* const* d_in, const int* in_sizes, int n_in,
                              void* d_out, int out_size) {
    const float* lbm  = (const float*)d_in[0];   // [N,3] float32
    const float* mass = (const float*)d_in[1];   // [N]   float32
    const float* lf   = (const float*)d_in[2];   // [51]  float32
    float* out = (float*)d_out;                  // [90,20,6] float32

    int n = in_sizes[1];
    int grid = (n + PART_PER_BLOCK - 1) / PART_PER_BLOCK;
    if (grid < 1) grid = 1;

    hist_kernel<<<grid, THREADS>>>(lbm, mass, n);

    conv_zero_kernel<<<(N_LB + LB_PER_BLOCK - 1) / LB_PER_BLOCK, THREADS>>>(lf, out);
}